// round 4
// baseline (speedup 1.0000x reference)
#include <cuda_runtime.h>
#include <math_constants.h>

#define N_PRED 8192
#define M_GT   32768
#define NSEG_A 8                      // segments over M (pass A: pred -> gt)
#define NSEG_B 8                      // segments over N (pass B: gt -> pred)
#define SEG_A  (M_GT / NSEG_A)        // 4096
#define SEG_B  (N_PRED / NSEG_B)      // 1024
#define TILE   1024
#define BLK    256

// Scratch (no allocations allowed): per-(query, segment) partial argmins.
__device__ float g_dA[N_PRED * NSEG_A];
__device__ int   g_jA[N_PRED * NSEG_A];
__device__ float g_dB[M_GT * NSEG_B];
__device__ int   g_iB[M_GT * NSEG_B];
__device__ float g_sumA[N_PRED / BLK];   // 32 block partials
__device__ float g_sumB[M_GT / BLK];     // 128 block partials

// One query point per thread; reference points streamed through a broadcast
// smem tile as (x, y, z, |r|^2). Distance uses the reference's expanded form
// pp + gg - 2*dot so fp32 near-ties resolve like the reference argmin.
// Strict '<' preserves first-min tie semantics within the ascending j scan.
__global__ void nn_seg_kernel(const float* __restrict__ Q,
                              const float* __restrict__ R,
                              float* __restrict__ bestD,
                              int* __restrict__ bestJ,
                              int segLen, int nSeg) {
    __shared__ float4 tile[TILE];

    const int qi = blockIdx.x * BLK + threadIdx.x;
    const float px = Q[3 * qi + 0];
    const float py = Q[3 * qi + 1];
    const float pz = Q[3 * qi + 2];
    const float pp = px * px + py * py + pz * pz;
    const float nx = -2.0f * px, ny = -2.0f * py, nz = -2.0f * pz;

    const int j0 = blockIdx.y * segLen;
    float bd = CUDART_INF_F;
    int   bj = j0;

    for (int tbase = 0; tbase < segLen; tbase += TILE) {
        __syncthreads();
        for (int t = threadIdx.x; t < TILE; t += BLK) {
            const int j = j0 + tbase + t;
            const float gx = R[3 * j + 0];
            const float gy = R[3 * j + 1];
            const float gz = R[3 * j + 2];
            tile[t] = make_float4(gx, gy, gz, gx * gx + gy * gy + gz * gz);
        }
        __syncthreads();

        #pragma unroll 8
        for (int t = 0; t < TILE; ++t) {
            const float4 g = tile[t];
            const float d = fmaf(nx, g.x, fmaf(ny, g.y, fmaf(nz, g.z, pp + g.w)));
            if (d < bd) { bd = d; bj = j0 + tbase + t; }
        }
    }

    bestD[qi * nSeg + blockIdx.y] = bd;
    bestJ[qi * nSeg + blockIdx.y] = bj;
}

// Resolve segment partials in ascending segment order (first-min tie
// semantics), gather the matched normal, accumulate 1 - <n_q, n_match> into
// a deterministic per-block partial sum.
__global__ void reduce_kernel(const float* __restrict__ bestD,
                              const int* __restrict__ bestJ,
                              const float* __restrict__ qN,
                              const float* __restrict__ rN,
                              int nSeg,
                              float* __restrict__ partial) {
    const int qi = blockIdx.x * BLK + threadIdx.x;

    float bd = CUDART_INF_F;
    int   bj = 0;
    for (int s = 0; s < nSeg; ++s) {
        const float d = bestD[qi * nSeg + s];
        if (d < bd) { bd = d; bj = bestJ[qi * nSeg + s]; }
    }

    const float v = 1.0f - (qN[3 * qi + 0] * rN[3 * bj + 0] +
                            qN[3 * qi + 1] * rN[3 * bj + 1] +
                            qN[3 * qi + 2] * rN[3 * bj + 2]);

    __shared__ float sm[BLK];
    sm[threadIdx.x] = v;
    __syncthreads();
    #pragma unroll
    for (int off = BLK / 2; off > 0; off >>= 1) {
        if (threadIdx.x < off) sm[threadIdx.x] += sm[threadIdx.x + off];
        __syncthreads();
    }
    if (threadIdx.x == 0) partial[blockIdx.x] = sm[0];
}

__global__ void finalize_kernel(float* __restrict__ out) {
    if (threadIdx.x == 0) {
        float sA = 0.0f;
        #pragma unroll
        for (int i = 0; i < N_PRED / BLK; ++i) sA += g_sumA[i];
        float sB = 0.0f;
        for (int i = 0; i < M_GT / BLK; ++i) sB += g_sumB[i];
        out[0] = sA * (1.0f / N_PRED) + sB * (1.0f / M_GT);
    }
}

extern "C" void kernel_launch(void* const* d_in, const int* in_sizes, int n_in,
                              void* d_out, int out_size) {
    const float* pred_pts = (const float*)d_in[0];  // [1, 8192, 3]
    const float* pred_nrm = (const float*)d_in[1];  // [1, 8192, 3]
    const float* gt_pts   = (const float*)d_in[2];  // [1, 32768, 3]
    const float* gt_nrm   = (const float*)d_in[3];  // [1, 32768, 3]
    float* out = (float*)d_out;

    float *dA, *dB, *sA, *sB;
    int *jA, *iB;
    cudaGetSymbolAddress((void**)&dA, g_dA);
    cudaGetSymbolAddress((void**)&jA, g_jA);
    cudaGetSymbolAddress((void**)&dB, g_dB);
    cudaGetSymbolAddress((void**)&iB, g_iB);
    cudaGetSymbolAddress((void**)&sA, g_sumA);
    cudaGetSymbolAddress((void**)&sB, g_sumB);

    // Pass A: for each predicted point, nearest gt point (argmin over M).
    {
        dim3 grid(N_PRED / BLK, NSEG_A);
        nn_seg_kernel<<<grid, BLK>>>(pred_pts, gt_pts, dA, jA, SEG_A, NSEG_A);
    }
    // Pass B: for each gt point, nearest predicted point (argmin over N).
    {
        dim3 grid(M_GT / BLK, NSEG_B);
        nn_seg_kernel<<<grid, BLK>>>(gt_pts, pred_pts, dB, iB, SEG_B, NSEG_B);
    }

    reduce_kernel<<<N_PRED / BLK, BLK>>>(dA, jA, pred_nrm, gt_nrm, NSEG_A, sA);
    reduce_kernel<<<M_GT / BLK, BLK>>>(dB, iB, gt_nrm, pred_nrm, NSEG_B, sB);

    finalize_kernel<<<1, 32>>>(out);
}